// round 2
// baseline (speedup 1.0000x reference)
#include <cuda_runtime.h>
#include <math.h>

#define S 1024
#define U 128
#define D 64
#define EPS 1e-7f
#define MARGIN 0.5f

// Scratch (device globals — no allocation allowed)
__device__ float g_centT[D * S];   // transposed centroids: [d][s], for coalesced GEMV
__device__ float g_sel[S * D];     // hardest utterance per speaker
__device__ float g_intra[S];       // intra_d per speaker

// ---------------------------------------------------------------------------
// Kernel 1: per-speaker centroid + normalize + intra max/argmax + select
// grid = S blocks, 128 threads
// ---------------------------------------------------------------------------
__global__ __launch_bounds__(128) void k_centroid_intra(const float* __restrict__ x) {
    const int s = blockIdx.x;
    const int t = threadIdx.x;

    // Row-padded x tile: stride 65 floats -> conflict-free stride-64 column reads
    __shared__ float sx[U * 65];          // 33280 B
    __shared__ float cent[D];
    __shared__ float csum[2][D];
    __shared__ float redv[U];
    __shared__ int   redi[U];
    __shared__ float s_inv_norm;

    // Cooperative load: 2048 float4 (32KB), de-vectorized into padded rows
    const float4* xs4 = (const float4*)(x + (size_t)s * (U * D));
    #pragma unroll
    for (int i = t; i < U * D / 4; i += 128) {
        float4 v = xs4[i];
        int u  = i >> 4;            // 16 float4 per row
        int d4 = (i & 15) << 2;
        float* p = &sx[u * 65 + d4];
        p[0] = v.x; p[1] = v.y; p[2] = v.z; p[3] = v.w;
    }
    __syncthreads();

    // Centroid mean: 128 threads = 2 halves x 64 dims
    {
        int d = t & 63, h = t >> 6;
        float sum = 0.f;
        int u0 = h * 64;
        #pragma unroll 8
        for (int u = u0; u < u0 + 64; u++) sum += sx[u * 65 + d];
        csum[h][d] = sum;
    }
    __syncthreads();
    if (t < D) cent[t] = (csum[0][t] + csum[1][t]) * (1.0f / (float)U);
    __syncthreads();

    // L2 norm (warp 0)
    if (t < 32) {
        float v = cent[t] * cent[t] + cent[t + 32] * cent[t + 32];
        #pragma unroll
        for (int o = 16; o; o >>= 1) v += __shfl_down_sync(0xffffffffu, v, o);
        if (t == 0) s_inv_norm = 1.0f / fmaxf(sqrtf(v), 1e-12f);
    }
    __syncthreads();
    if (t < D) cent[t] *= s_inv_norm;
    __syncthreads();

    // Intra: thread u computes dot(x[s,u], cent); clip; min + first-index
    {
        float dot = 0.f;
        const float* row = &sx[t * 65];
        #pragma unroll
        for (int d = 0; d < D; d++) dot = fmaf(row[d], cent[d], dot);
        float c = fminf(fmaxf(dot, -1.0f + EPS), 1.0f - EPS);
        redv[t] = c;
        redi[t] = t;
    }
    __syncthreads();
    // min-value reduce, first-index tie-break (on clipped value — faithful)
    for (int off = 64; off >= 1; off >>= 1) {
        if (t < off) {
            float a = redv[t], b = redv[t + off];
            int ai = redi[t], bi = redi[t + off];
            if (b < a || (b == a && bi < ai)) { redv[t] = b; redi[t] = bi; }
        }
        __syncthreads();
    }

    if (t == 0) g_intra[s] = acosf(redv[0]);
    int idx = redi[0];
    if (t < D) {
        g_sel[s * D + t]    = sx[idx * 65 + t];
        g_centT[t * S + s]  = cent[t];     // transposed store for K2 coalescing
    }
}

// ---------------------------------------------------------------------------
// Kernel 2: dots = sel @ centroids^T (8 rows per block), gather-max over the
// tiled index pattern, hinge term, atomic accumulate into d_out.
// grid = S/8 = 128 blocks, 256 threads
// ---------------------------------------------------------------------------
__global__ __launch_bounds__(256) void k_inter_loss(float* __restrict__ out) {
    const int j0 = blockIdx.x * 8;
    const int t  = threadIdx.x;

    __shared__ float sdots[8][S];    // 32 KB
    __shared__ float ssel[8][D];     // 2 KB

    for (int i = t; i < 8 * D; i += 256)
        ssel[i >> 6][i & 63] = g_sel[(j0 + (i >> 6)) * D + (i & 63)];
    __syncthreads();

    // GEMV: thread t owns columns c = t + {0,256,512,768}
    float acc[8][4];
    #pragma unroll
    for (int r = 0; r < 8; r++)
        #pragma unroll
        for (int cc = 0; cc < 4; cc++) acc[r][cc] = 0.f;

    #pragma unroll 4
    for (int d = 0; d < D; d++) {
        const float* ct = &g_centT[d * S];
        float c0 = ct[t];
        float c1 = ct[t + 256];
        float c2 = ct[t + 512];
        float c3 = ct[t + 768];
        #pragma unroll
        for (int r = 0; r < 8; r++) {
            float sv = ssel[r][d];
            acc[r][0] = fmaf(sv, c0, acc[r][0]);
            acc[r][1] = fmaf(sv, c1, acc[r][1]);
            acc[r][2] = fmaf(sv, c2, acc[r][2]);
            acc[r][3] = fmaf(sv, c3, acc[r][3]);
        }
    }
    #pragma unroll
    for (int r = 0; r < 8; r++) {
        sdots[r][t]       = acc[r][0];
        sdots[r][t + 256] = acc[r][1];
        sdots[r][t + 512] = acc[r][2];
        sdots[r][t + 768] = acc[r][3];
    }
    __syncthreads();

    // Gather-max: warp w handles row j0+w. Pattern: for flat m = j*1023+q,
    // centroid index c = ((m>>10) + 1 + (m & 1023)) & 1023.
    const int w = t >> 5, lane = t & 31;
    const int j = j0 + w;
    float mx = -3.4e38f;
    for (int q = lane; q < S - 1; q += 32) {
        int m = j * (S - 1) + q;
        int c = ((m >> 10) + 1 + (m & (S - 1))) & (S - 1);
        mx = fmaxf(mx, sdots[w][c]);
    }
    #pragma unroll
    for (int o = 16; o; o >>= 1) mx = fmaxf(mx, __shfl_down_sync(0xffffffffu, mx, o));

    if (lane == 0) {
        float md = fminf(fmaxf(mx, -1.0f + EPS), 1.0f - EPS);
        float inter_d = acosf(md);
        float term = fmaxf(MARGIN + g_intra[j] - inter_d, 0.0f);
        atomicAdd(out, term);
    }
}

__global__ void k_zero(float* out) { out[0] = 0.0f; }

extern "C" void kernel_launch(void* const* d_in, const int* in_sizes, int n_in,
                              void* d_out, int out_size) {
    const float* x = (const float*)d_in[0];
    float* out = (float*)d_out;

    k_zero<<<1, 1>>>(out);
    k_centroid_intra<<<S, 128>>>(x);
    k_inter_loss<<<S / 8, 256>>>(out);
}